// round 15
// baseline (speedup 1.0000x reference)
#include <cuda_runtime.h>
#include <math.h>

#define NPIX (512*512)
#define NB 16
#define SIG 0.125f
#define TAUC 0.125f
#define ALPHA_C 0.15f
#define MU_C 10.0f
#define EPS_C 1e-6f
#define INV1T (1.0f/1.125f)
#define FRLO 0.43000000000029104f
#define FRHI 0.5699999999953434f

// fused PD tiling (shuffle version, FROZEN R7 inner loop)
#define TT 44
#define KK 10
#define SS 64
#define PPT 8
#define NTILE 12            // ceil(512/44)

// ---------------- device scratch ----------------
__device__ float g_tmpR[NB*NPIX];
__device__ float g_tmpM[NB*NPIX];
__device__ float g_x  [NB*NPIX];
__device__ float g_Nh [NB*NPIX];
__device__ float g_gm [NB*NPIX];
__device__ float g_u [2][NB*NPIX];
__device__ float g_ub[2][NB*NPIX];
__device__ float g_px[2][NB*NPIX];
__device__ float g_py[2][NB*NPIX];

// radix 8+8+8+8 (R7 scheme — final)
__device__ unsigned g_hist1 [NB*256];      // x pass-1
__device__ unsigned g_hist1g[NB*256];      // gm pass-1
__device__ unsigned g_histX[3][64*256];    // x passes 2..4
__device__ unsigned g_histG[3][32*256];    // gm passes 2..4
__device__ float    g_isig[NB];

__constant__ int c_ranksX[4] = {2621, 2622, 259521, 259522};
__constant__ int c_ranksG[2] = {131071, 131072};

// ---------------- warp-collective radix resolve (256-bin) ----------------
__device__ __forceinline__ unsigned warp_resolve_step(const unsigned* hist, unsigned& rank, int lane) {
    unsigned c[8]; unsigned s = 0;
    #pragma unroll
    for (int i = 0; i < 8; i++) { c[i] = __ldg(&hist[lane*8 + i]); s += c[i]; }
    unsigned pre = s;
    #pragma unroll
    for (int d = 1; d < 32; d <<= 1) {
        unsigned v = __shfl_up_sync(0xffffffffu, pre, d);
        if (lane >= d) pre += v;
    }
    unsigned excl = pre - s;
    bool hit = (rank >= excl) && (rank < excl + s);
    unsigned m = __ballot_sync(0xffffffffu, hit);
    int hl = m ? (__ffs(m) - 1) : 31;
    unsigned bkt = 255, rr = 0;
    if (lane == hl) {
        if (m) {
            rr = rank - excl;
            int i = 0;
            while (i < 7 && rr >= c[i]) { rr -= c[i]; i++; }
            bkt = (unsigned)(hl*8 + i);
        } else { bkt = 255; rr = 0; }
    }
    bkt = __shfl_sync(0xffffffffu, bkt, hl);
    rr  = __shfl_sync(0xffffffffu, rr,  hl);
    rank = rr;
    return bkt;
}

__device__ __forceinline__ unsigned chain_prefix(int which, int b, int tgt, int upto, int lane) {
    unsigned rank = which ? (unsigned)c_ranksG[tgt] : (unsigned)c_ranksX[tgt];
    unsigned prefix = 0u;
    for (int pass = 1; pass <= upto; pass++) {
        const unsigned* hist;
        if (pass == 1) hist = (which ? g_hist1g : g_hist1) + b*256;
        else {
            int perB = which ? 2 : 4;
            hist = (which ? &g_histG[pass-2][0] : &g_histX[pass-2][0]) + (b*perB + tgt)*256;
        }
        unsigned bkt = warp_resolve_step(hist, rank, lane);
        prefix |= bkt << (8*(4-pass));
    }
    return prefix;
}

// ---------------- horizontal 31-max-pool (padded smem) + hist zeroing fold ----------------
__global__ void k_hpool(const float* __restrict__ Iy) {
    int row = blockIdx.x, b = blockIdx.y;
    __shared__ float sR[542];
    __shared__ float sM[542];
    int j = threadIdx.x;

    // fold: zero all histogram buffers (10 words per block x 8192 blocks = 81920)
    {
        int bid = b * 512 + row;
        if (j < 10) {
            int idx = bid * 10 + j;
            if (idx < 4096) g_hist1[idx] = 0;
            else if (idx < 8192) g_hist1g[idx - 4096] = 0;
            else if (idx < 57344) (&g_histX[0][0])[idx - 8192] = 0;
            else (&g_histG[0][0])[idx - 57344] = 0;
        }
    }

    const float* base = Iy + (size_t)b*3*NPIX + (size_t)row*512;
    float r = __ldg(base + j);
    float m = fmaxf(__ldg(base + NPIX + j), __ldg(base + 2*NPIX + j));
    sR[j + 15] = r; sM[j + 15] = m;
    if (j < 15) {
        float r0 = __ldg(base);
        float m0 = fmaxf(__ldg(base + NPIX), __ldg(base + 2*NPIX));
        sR[j] = r0; sM[j] = m0;
        float r1 = __ldg(base + 511);
        float m1 = fmaxf(__ldg(base + NPIX + 511), __ldg(base + 2*NPIX + 511));
        sR[527 + j] = r1; sM[527 + j] = m1;
    }
    __syncthreads();
    float mr = r, mm = m;
    #pragma unroll
    for (int t = -15; t <= 15; t++) {
        mr = fmaxf(mr, sR[j + 15 + t]);
        mm = fmaxf(mm, sM[j + 15 + t]);
    }
    size_t o = (size_t)b*NPIX + (size_t)row*512 + j;
    g_tmpR[o] = mr; g_tmpM[o] = mm;
}

// ---------------- vertical 31-max-pool + x + x pass-1 histogram ----------------
__global__ void k_vpool_x(const float* __restrict__ Iy) {
    int b = blockIdx.z;
    int col0 = blockIdx.x * 32;
    int row0 = blockIdx.y * 64;
    __shared__ float sR[94][32];
    __shared__ float sM[94][32];
    __shared__ unsigned h[8*256];
    int tid = threadIdx.y * 32 + threadIdx.x;
    for (int i = tid; i < 8*256; i += 256) h[i] = 0;
    for (int idx = tid; idx < 94*32; idx += 256) {
        int rr = idx >> 5, cc = idx & 31;
        int gr = row0 + rr - 15; gr = gr < 0 ? 0 : (gr > 511 ? 511 : gr);
        size_t o = (size_t)b*NPIX + (size_t)gr*512 + col0 + cc;
        sR[rr][cc] = g_tmpR[o];
        sM[rr][cc] = g_tmpM[o];
    }
    __syncthreads();
    int tx = threadIdx.x;
    unsigned rep = (tid & 7) * 256;
    for (int k = 0; k < 8; k++) {
        int r = threadIdx.y * 8 + k;
        float mr = -1e30f, mm = -1e30f;
        #pragma unroll
        for (int t = 0; t < 31; t++) {
            mr = fmaxf(mr, sR[r+t][tx]);
            mm = fmaxf(mm, sM[r+t][tx]);
        }
        int gr = row0 + r;
        size_t o = (size_t)b*NPIX + (size_t)gr*512 + col0 + tx;
        float R = __ldg(Iy + (size_t)b*3*NPIX + (size_t)gr*512 + col0 + tx);
        float xv = fabsf(mr - mm) + R;
        g_x[o] = xv;
        atomicAdd(&h[rep + (__float_as_uint(xv) >> 24)], 1u);
    }
    __syncthreads();
    for (int i = tid; i < 256; i += 256) {
        unsigned s = 0;
        #pragma unroll
        for (int r = 0; r < 8; r++) s += h[r*256 + i];
        if (s) atomicAdd(&g_hist1[b*256 + i], s);
    }
}

// ---------------- conditional histogram; prefix-chain prologue (R14 body) ----------------
__global__ void k_histT(int which, int pass) {
    int b = blockIdx.y;
    const int perB = which ? 2 : 4;
    const float* src = which ? g_gm : g_x;
    unsigned* gh = which ? &g_histG[pass-2][0] : &g_histX[pass-2][0];
    int shift = 8 * (4 - pass);
    unsigned mask = 0xFFFFFFFFu << (shift + 8);

    __shared__ unsigned s_pref[4];
    __shared__ unsigned h[2][4*256];
    int warp = threadIdx.x >> 5, lane = threadIdx.x & 31;
    for (int i = threadIdx.x; i < 2*4*256; i += blockDim.x) (&h[0][0])[i] = 0;
    if (warp < perB) {
        unsigned p = chain_prefix(which, b, warp, pass - 1, lane);
        if (lane == 0) s_pref[warp] = p;
    }
    __syncthreads();

    unsigned pref[4];
    #pragma unroll
    for (int j = 0; j < 4; j++) pref[j] = (j < perB) ? s_pref[j] : 0xFFFFFFFFu;

    unsigned rep = threadIdx.x & 1;
    const float4* p = (const float4*)(src + (size_t)b*NPIX);
    const int stride = gridDim.x * blockDim.x;     // 8192
    int i0 = blockIdx.x * blockDim.x + threadIdx.x;
    for (int base_i = i0; base_i < NPIX/4; base_i += 4*stride) {
        float4 v0 = __ldg(p + base_i);
        float4 v1 = __ldg(p + base_i + stride);
        float4 v2 = __ldg(p + base_i + 2*stride);
        float4 v3 = __ldg(p + base_i + 3*stride);
        float4 vv[4] = {v0, v1, v2, v3};
        #pragma unroll
        for (int q = 0; q < 4; q++) {
            unsigned vs[4] = {__float_as_uint(vv[q].x), __float_as_uint(vv[q].y),
                              __float_as_uint(vv[q].z), __float_as_uint(vv[q].w)};
            #pragma unroll
            for (int e = 0; e < 4; e++) {
                unsigned v = vs[e];
                unsigned vm = v & mask;
                unsigned bin = (v >> shift) & 0xFFu;
                #pragma unroll
                for (int j = 0; j < 4; j++)
                    if (j < perB && vm == pref[j]) atomicAdd(&h[rep][j*256 + bin], 1u);
            }
        }
    }
    __syncthreads();
    for (int i = threadIdx.x; i < perB*256; i += blockDim.x) {
        unsigned s = h[0][i] + h[1][i];
        if (s) atomicAdd(&gh[(b*perB + (i >> 8))*256 + (i & 255)], s);
    }
}

// ---------------- N_hat + grad mag + gm pass-1 histogram; x-resolve prologue ----------------
__global__ void k_nhat() {
    int b = blockIdx.y;
    __shared__ unsigned h[8*256];
    __shared__ float s_sel[4];
    int warp = threadIdx.x >> 5, lane = threadIdx.x & 31;
    for (int i = threadIdx.x; i < 8*256; i += blockDim.x) h[i] = 0;
    if (warp < 4) {
        unsigned p = chain_prefix(0, b, warp, 4, lane);
        if (lane == 0) s_sel[warp] = __uint_as_float(p);
    }
    __syncthreads();
    float lo = s_sel[0]*(1.0f-FRLO) + s_sel[1]*FRLO;
    float hi = s_sel[2]*(1.0f-FRHI) + s_sel[3]*FRHI;
    float inv = 1.0f / (hi - lo + EPS_C);

    unsigned rep = (threadIdx.x & 7) * 256;
    size_t base = (size_t)b*NPIX;
    for (int idx = blockIdx.x * blockDim.x + threadIdx.x; idx < NPIX; idx += 64*256) {
        int i = idx >> 9, j = idx & 511;
        size_t o = base + idx;
        float xc = __ldg(&g_x[o]);
        float n00 = fminf(fmaxf((xc - lo) * inv, 0.0f), 1.0f);
        float dx = 0.0f, dy = 0.0f;
        if (j < 511) {
            float xr = __ldg(&g_x[o + 1]);
            dx = fminf(fmaxf((xr - lo) * inv, 0.0f), 1.0f) - n00;
        }
        if (i < 511) {
            float xd = __ldg(&g_x[o + 512]);
            dy = fminf(fmaxf((xd - lo) * inv, 0.0f), 1.0f) - n00;
        }
        float gm = sqrtf(dx*dx + dy*dy + EPS_C);
        g_Nh[o] = n00;
        g_gm[o] = gm;
        atomicAdd(&h[rep + (__float_as_uint(gm) >> 24)], 1u);
    }
    __syncthreads();
    for (int i = threadIdx.x; i < 256; i += blockDim.x) {
        unsigned s = 0;
        #pragma unroll
        for (int r = 0; r < 8; r++) s += h[r*256 + i];
        if (s) atomicAdd(&g_hist1g[b*256 + i], s);
    }
}

// ---------------- tiny isig resolve (replaces k_wxy's prologue) ----------------
__global__ void k_isig() {
    int b = blockIdx.x;
    __shared__ float s_sel[2];
    int warp = threadIdx.x >> 5, lane = threadIdx.x & 31;
    if (warp < 2) {
        unsigned p = chain_prefix(1, b, warp, 4, lane);
        if (lane == 0) s_sel[warp] = __uint_as_float(p);
    }
    __syncthreads();
    if (threadIdx.x == 0) {
        float med = 0.5f * (s_sel[0] + s_sel[1]);
        g_isig[b] = 1.0f / fmaxf(med, EPS_C);
    }
}

// ---------------- shuffle-register fused PD ----------------
// Inner loop: FROZEN byte-identical R7 body. Prologue now computes the
// bounds s_bx/s_by from g_Nh + isig directly (identical expressions and op
// order to the old k_wxy -> bit-identical values), eliminating the k_wxy
// kernel and the g_Wx/g_Wy arrays entirely.
template<bool FIRST, bool LAST>
__global__ void __launch_bounds__(512, 2) k_pdshfl(int rd, int wr, float* __restrict__ out) {
    extern __shared__ float sm[];
    float* s_bx     = sm;
    float* s_by     = sm + SS*SS;
    float* s_tnh    = sm + 2*SS*SS;
    float* s_rowub  = sm + 3*SS*SS;          // [9][SS]
    float* s_rowpy  = s_rowub + 9*SS;        // [9][SS]
    float* s_seamub = s_rowpy + 9*SS;        // [SS]
    float* s_seampx = s_seamub + SS;         // [SS]

    int b = blockIdx.z;
    int rx0 = blockIdx.x * TT - KK;
    int ry0 = blockIdx.y * TT - KK;
    size_t base = (size_t)b * NPIX;
    int tx = threadIdx.x, ty = threadIdx.y;
    int R0 = ty * PPT;
    int gj = rx0 + tx;
    int gi0 = ry0 + R0;
    bool jok = (gj >= 0) && (gj < 512);

    const unsigned FULL = 0xffffffffu;
    float ru[PPT], rub[PPT], rpx[PPT], rpy[PPT];
    float rnh[PPT];

    // ---- prologue pass 1: load nh + state ----
    #pragma unroll
    for (int k = 0; k < PPT; k++) {
        int gi = gi0 + k;
        int o = (R0 + k)*SS + tx;
        bool val = jok && gi >= 0 && gi < 512;
        size_t go = base + (size_t)gi*512 + gj;
        float nh = val ? __ldg(&g_Nh[go]) : 0.0f;
        rnh[k] = nh;
        if (val) {
            s_tnh[o] = TAUC * nh;
            if (FIRST) {
                ru[k] = nh; rub[k] = nh; rpx[k] = 0.0f; rpy[k] = 0.0f;
            } else {
                ru[k]  = __ldg(&g_u [rd][go]);
                rub[k] = __ldg(&g_ub[rd][go]);
                rpx[k] = __ldg(&g_px[rd][go]);
                rpy[k] = __ldg(&g_py[rd][go]);
            }
        } else {
            s_tnh[o] = 0.0f;
            ru[k] = 0.0f; rub[k] = 0.0f; rpx[k] = 0.0f; rpy[k] = 0.0f;
        }
    }

    // ---- prologue pass 2: bounds bx/by (bit-identical to old k_wxy) ----
    {
        float isig = __ldg(&g_isig[b]);
        #pragma unroll
        for (int k = 0; k < PPT; k++) {
            int gi = gi0 + k;
            int o = (R0 + k)*SS + tx;
            bool val = jok && gi >= 0 && gi < 512;
            float nh = rnh[k];
            float nhR = __shfl_down_sync(FULL, nh, 1);
            if ((tx == 31 || tx == 63) && val && gj < 511)
                nhR = __ldg(&g_Nh[base + (size_t)gi*512 + gj + 1]);
            float nhD = (k < PPT-1) ? rnh[k+1] : 0.0f;
            if (k == PPT-1 && val && gi < 511)
                nhD = __ldg(&g_Nh[base + (size_t)(gi+1)*512 + gj]);
            float dx = (gj < 511) ? (nhR - nh) : 0.0f;
            float dy = (gi < 511) ? (nhD - nh) : 0.0f;
            if (val) {
                s_bx[o] = ALPHA_C * (1.0f + MU_C * __expf(-fabsf(dx) * isig));
                s_by[o] = ALPHA_C * (1.0f + MU_C * __expf(-fabsf(dy) * isig));
            } else {
                s_bx[o] = 0.0f; s_by[o] = 0.0f;
            }
        }
    }

    s_rowub[ty*SS + tx] = rub[0];
    if (ty == 0) { s_rowub[8*SS + tx] = 0.0f; s_rowpy[0*SS + tx] = 0.0f; }
    if (tx == 32) {
        #pragma unroll
        for (int k = 0; k < PPT; k++) s_seamub[R0 + k] = rub[k];
    }
    __syncthreads();

    bool jlt511 = (gj < 511);
    bool jgt0   = (gj > 0);

    for (int t = 0; t < KK; t++) {
        float ubbelow = s_rowub[(ty+1)*SS + tx];
        #pragma unroll
        for (int k = 0; k < PPT; k++) {
            float ubc = rub[k];
            float ubr = __shfl_down_sync(FULL, ubc, 1);
            if (tx == 31) ubr = s_seamub[R0 + k];
            float ubd = (k < PPT-1) ? rub[k+1] : ubbelow;
            int gi = gi0 + k;
            float dx = jlt511     ? (ubr - ubc) : 0.0f;
            float dy = (gi < 511) ? (ubd - ubc) : 0.0f;
            int o = (R0 + k)*SS + tx;
            float bx = s_bx[o], by = s_by[o];
            rpx[k] = fminf(fmaxf(rpx[k] + SIG*dx, -bx), bx);
            rpy[k] = fminf(fmaxf(rpy[k] + SIG*dy, -by), by);
        }
        s_rowpy[(ty+1)*SS + tx] = rpy[PPT-1];
        if (tx == 31) {
            #pragma unroll
            for (int k = 0; k < PPT; k++) s_seampx[R0 + k] = rpx[k];
        }
        __syncthreads();

        float pyabove = s_rowpy[ty*SS + tx];
        #pragma unroll
        for (int k = 0; k < PPT; k++) {
            float pxc = rpx[k];
            float pxl = __shfl_up_sync(FULL, pxc, 1);
            if (tx == 32) pxl = s_seampx[R0 + k];
            if (!jgt0) pxl = 0.0f;
            float pyu = (k > 0) ? rpy[k-1] : pyabove;
            int gi = gi0 + k;
            if (gi <= 0) pyu = 0.0f;
            int o = (R0 + k)*SS + tx;
            float uc = ru[k];
            float un = (uc + TAUC*(rpx[k] - pxl + rpy[k] - pyu) + s_tnh[o]) * INV1T;
            rub[k] = 2.0f*un - uc;
            ru[k] = un;
        }
        s_rowub[ty*SS + tx] = rub[0];
        if (tx == 32) {
            #pragma unroll
            for (int k = 0; k < PPT; k++) s_seamub[R0 + k] = rub[k];
        }
        __syncthreads();
    }

    if (tx >= KK && tx < KK+TT && gj < 512) {
        #pragma unroll
        for (int k = 0; k < PPT; k++) {
            int r = R0 + k;
            if (r >= KK && r < KK+TT) {
                int gi = gi0 + k;
                if (gi < 512) {
                    size_t go = base + (size_t)gi*512 + gj;
                    if (LAST) {
                        out[go] = fminf(fmaxf(ru[k], 0.0f), 1.0f);
                    } else {
                        g_u [wr][go] = ru[k];
                        g_ub[wr][go] = rub[k];
                        g_px[wr][go] = rpx[k];
                        g_py[wr][go] = rpy[k];
                    }
                }
            }
        }
    }
}

// ---------------- launch (single stream, no device allocations) ----------------
extern "C" void kernel_launch(void* const* d_in, const int* in_sizes, int n_in,
                              void* d_out, int out_size) {
    const float* Iy = (const float*)d_in[0];
    float* out = (float*)d_out;

    const int smbytes = (3*SS*SS + 2*9*SS + 2*SS) * (int)sizeof(float);
    cudaFuncSetAttribute(k_pdshfl<true,false>,  cudaFuncAttributeMaxDynamicSharedMemorySize, smbytes);
    cudaFuncSetAttribute(k_pdshfl<false,false>, cudaFuncAttributeMaxDynamicSharedMemorySize, smbytes);
    cudaFuncSetAttribute(k_pdshfl<false,true>,  cudaFuncAttributeMaxDynamicSharedMemorySize, smbytes);

    dim3 b32x8(32, 8);

    k_hpool  <<<dim3(512, NB), 512>>>(Iy);       // + histogram zeroing fold
    k_vpool_x<<<dim3(16, 8, NB), b32x8>>>(Iy);   // + x pass-1 histogram

    // x quantiles (resolve chains run inside consumers)
    k_histT<<<dim3(32, NB), 256>>>(0, 2);
    k_histT<<<dim3(32, NB), 256>>>(0, 3);
    k_histT<<<dim3(32, NB), 256>>>(0, 4);

    k_nhat<<<dim3(64, NB), 256>>>();             // x-resolve prologue + gm pass-1

    // gm quantiles
    k_histT<<<dim3(32, NB), 256>>>(1, 2);
    k_histT<<<dim3(32, NB), 256>>>(1, 3);
    k_histT<<<dim3(32, NB), 256>>>(1, 4);

    k_isig<<<NB, 64>>>();                        // gm-resolve -> g_isig (k_wxy deleted)

    // 30 PD iterations = 3 fused launches of 10
    dim3 bTile(SS, 8);
    dim3 gTile(NTILE, NTILE, NB);
    k_pdshfl<true,  false><<<gTile, bTile, smbytes>>>(0, 0, nullptr);
    k_pdshfl<false, false><<<gTile, bTile, smbytes>>>(0, 1, nullptr);
    k_pdshfl<false, true ><<<gTile, bTile, smbytes>>>(1, 0, out);
}

// round 16
// speedup vs baseline: 1.0072x; 1.0072x over previous
#include <cuda_runtime.h>
#include <math.h>

#define NPIX (512*512)
#define NB 16
#define SIG 0.125f
#define TAUC 0.125f
#define ALPHA_C 0.15f
#define MU_C 10.0f
#define EPS_C 1e-6f
#define INV1T (1.0f/1.125f)
#define FRLO 0.43000000000029104f
#define FRHI 0.5699999999953434f

// fused PD tiling (shuffle version, FROZEN R7/R14)
#define TT 44
#define KK 10
#define SS 64
#define PPT 8
#define NTILE 12            // ceil(512/44)

// ---------------- device scratch ----------------
__device__ float g_tmpR[NB*NPIX];
__device__ float g_tmpM[NB*NPIX];
__device__ float g_x  [NB*NPIX];
__device__ float g_Nh [NB*NPIX];
__device__ float g_gm [NB*NPIX];
__device__ float g_Wx [NB*NPIX];   // ALPHA*Wx
__device__ float g_Wy [NB*NPIX];   // ALPHA*Wy
__device__ float g_u [2][NB*NPIX];
__device__ float g_ub[2][NB*NPIX];
__device__ float g_px[2][NB*NPIX];
__device__ float g_py[2][NB*NPIX];

// radix 8+8+8+8 (R7 scheme — final)
__device__ unsigned g_hist1 [NB*256];      // x pass-1
__device__ unsigned g_hist1g[NB*256];      // gm pass-1
__device__ unsigned g_histX[3][64*256];    // x passes 2..4
__device__ unsigned g_histG[3][32*256];    // gm passes 2..4

__constant__ int c_ranksX[4] = {2621, 2622, 259521, 259522};
__constant__ int c_ranksG[2] = {131071, 131072};

// ---------------- warp-collective radix resolve (256-bin) ----------------
__device__ __forceinline__ unsigned warp_resolve_step(const unsigned* hist, unsigned& rank, int lane) {
    unsigned c[8]; unsigned s = 0;
    #pragma unroll
    for (int i = 0; i < 8; i++) { c[i] = __ldg(&hist[lane*8 + i]); s += c[i]; }
    unsigned pre = s;
    #pragma unroll
    for (int d = 1; d < 32; d <<= 1) {
        unsigned v = __shfl_up_sync(0xffffffffu, pre, d);
        if (lane >= d) pre += v;
    }
    unsigned excl = pre - s;
    bool hit = (rank >= excl) && (rank < excl + s);
    unsigned m = __ballot_sync(0xffffffffu, hit);
    int hl = m ? (__ffs(m) - 1) : 31;
    unsigned bkt = 255, rr = 0;
    if (lane == hl) {
        if (m) {
            rr = rank - excl;
            int i = 0;
            while (i < 7 && rr >= c[i]) { rr -= c[i]; i++; }
            bkt = (unsigned)(hl*8 + i);
        } else { bkt = 255; rr = 0; }
    }
    bkt = __shfl_sync(0xffffffffu, bkt, hl);
    rr  = __shfl_sync(0xffffffffu, rr,  hl);
    rank = rr;
    return bkt;
}

__device__ __forceinline__ unsigned chain_prefix(int which, int b, int tgt, int upto, int lane) {
    unsigned rank = which ? (unsigned)c_ranksG[tgt] : (unsigned)c_ranksX[tgt];
    unsigned prefix = 0u;
    for (int pass = 1; pass <= upto; pass++) {
        const unsigned* hist;
        if (pass == 1) hist = (which ? g_hist1g : g_hist1) + b*256;
        else {
            int perB = which ? 2 : 4;
            hist = (which ? &g_histG[pass-2][0] : &g_histX[pass-2][0]) + (b*perB + tgt)*256;
        }
        unsigned bkt = warp_resolve_step(hist, rank, lane);
        prefix |= bkt << (8*(4-pass));
    }
    return prefix;
}

// ---------------- horizontal 31-max-pool (padded smem) + hist zeroing fold ----------------
__global__ void k_hpool(const float* __restrict__ Iy) {
    int row = blockIdx.x, b = blockIdx.y;
    __shared__ float sR[542];
    __shared__ float sM[542];
    int j = threadIdx.x;

    // fold: zero all histogram buffers (10 words per block x 8192 blocks >= 81920)
    {
        int bid = b * 512 + row;
        if (j < 10) {
            int idx = bid * 10 + j;
            if (idx < 4096) g_hist1[idx] = 0;
            else if (idx < 8192) g_hist1g[idx - 4096] = 0;
            else if (idx < 57344) (&g_histX[0][0])[idx - 8192] = 0;
            else if (idx < 81920) (&g_histG[0][0])[idx - 57344] = 0;
        }
    }

    const float* base = Iy + (size_t)b*3*NPIX + (size_t)row*512;
    float r = __ldg(base + j);
    float m = fmaxf(__ldg(base + NPIX + j), __ldg(base + 2*NPIX + j));
    sR[j + 15] = r; sM[j + 15] = m;
    if (j < 15) {
        float r0 = __ldg(base);
        float m0 = fmaxf(__ldg(base + NPIX), __ldg(base + 2*NPIX));
        sR[j] = r0; sM[j] = m0;
        float r1 = __ldg(base + 511);
        float m1 = fmaxf(__ldg(base + NPIX + 511), __ldg(base + 2*NPIX + 511));
        sR[527 + j] = r1; sM[527 + j] = m1;
    }
    __syncthreads();
    float mr = r, mm = m;
    #pragma unroll
    for (int t = -15; t <= 15; t++) {
        mr = fmaxf(mr, sR[j + 15 + t]);
        mm = fmaxf(mm, sM[j + 15 + t]);
    }
    size_t o = (size_t)b*NPIX + (size_t)row*512 + j;
    g_tmpR[o] = mr; g_tmpM[o] = mm;
}

// ---------------- vertical 31-max-pool + x + x pass-1 histogram ----------------
__global__ void k_vpool_x(const float* __restrict__ Iy) {
    int b = blockIdx.z;
    int col0 = blockIdx.x * 32;
    int row0 = blockIdx.y * 64;
    __shared__ float sR[94][32];
    __shared__ float sM[94][32];
    __shared__ unsigned h[8*256];
    int tid = threadIdx.y * 32 + threadIdx.x;
    for (int i = tid; i < 8*256; i += 256) h[i] = 0;
    for (int idx = tid; idx < 94*32; idx += 256) {
        int rr = idx >> 5, cc = idx & 31;
        int gr = row0 + rr - 15; gr = gr < 0 ? 0 : (gr > 511 ? 511 : gr);
        size_t o = (size_t)b*NPIX + (size_t)gr*512 + col0 + cc;
        sR[rr][cc] = g_tmpR[o];
        sM[rr][cc] = g_tmpM[o];
    }
    __syncthreads();
    int tx = threadIdx.x;
    unsigned rep = (tid & 7) * 256;
    for (int k = 0; k < 8; k++) {
        int r = threadIdx.y * 8 + k;
        float mr = -1e30f, mm = -1e30f;
        #pragma unroll
        for (int t = 0; t < 31; t++) {
            mr = fmaxf(mr, sR[r+t][tx]);
            mm = fmaxf(mm, sM[r+t][tx]);
        }
        int gr = row0 + r;
        size_t o = (size_t)b*NPIX + (size_t)gr*512 + col0 + tx;
        float R = __ldg(Iy + (size_t)b*3*NPIX + (size_t)gr*512 + col0 + tx);
        float xv = fabsf(mr - mm) + R;
        g_x[o] = xv;
        atomicAdd(&h[rep + (__float_as_uint(xv) >> 24)], 1u);
    }
    __syncthreads();
    for (int i = tid; i < 256; i += 256) {
        unsigned s = 0;
        #pragma unroll
        for (int r = 0; r < 8; r++) s += h[r*256 + i];
        if (s) atomicAdd(&g_hist1[b*256 + i], s);
    }
}

// ---------------- conditional histogram; prefix-chain prologue; MLP-4 (R14) ----------------
__global__ void k_histT(int which, int pass) {
    int b = blockIdx.y;
    const int perB = which ? 2 : 4;
    const float* src = which ? g_gm : g_x;
    unsigned* gh = which ? &g_histG[pass-2][0] : &g_histX[pass-2][0];
    int shift = 8 * (4 - pass);
    unsigned mask = 0xFFFFFFFFu << (shift + 8);

    __shared__ unsigned s_pref[4];
    __shared__ unsigned h[2][4*256];
    int warp = threadIdx.x >> 5, lane = threadIdx.x & 31;
    for (int i = threadIdx.x; i < 2*4*256; i += blockDim.x) (&h[0][0])[i] = 0;
    if (warp < perB) {
        unsigned p = chain_prefix(which, b, warp, pass - 1, lane);
        if (lane == 0) s_pref[warp] = p;
    }
    __syncthreads();

    unsigned pref[4];
    #pragma unroll
    for (int j = 0; j < 4; j++) pref[j] = (j < perB) ? s_pref[j] : 0xFFFFFFFFu;

    unsigned rep = threadIdx.x & 1;
    const float4* p = (const float4*)(src + (size_t)b*NPIX);
    const int stride = gridDim.x * blockDim.x;     // 8192
    int i0 = blockIdx.x * blockDim.x + threadIdx.x;
    for (int base_i = i0; base_i < NPIX/4; base_i += 4*stride) {
        float4 v0 = __ldg(p + base_i);
        float4 v1 = __ldg(p + base_i + stride);
        float4 v2 = __ldg(p + base_i + 2*stride);
        float4 v3 = __ldg(p + base_i + 3*stride);
        float4 vv[4] = {v0, v1, v2, v3};
        #pragma unroll
        for (int q = 0; q < 4; q++) {
            unsigned vs[4] = {__float_as_uint(vv[q].x), __float_as_uint(vv[q].y),
                              __float_as_uint(vv[q].z), __float_as_uint(vv[q].w)};
            #pragma unroll
            for (int e = 0; e < 4; e++) {
                unsigned v = vs[e];
                unsigned vm = v & mask;
                unsigned bin = (v >> shift) & 0xFFu;
                #pragma unroll
                for (int j = 0; j < 4; j++)
                    if (j < perB && vm == pref[j]) atomicAdd(&h[rep][j*256 + bin], 1u);
            }
        }
    }
    __syncthreads();
    for (int i = threadIdx.x; i < perB*256; i += blockDim.x) {
        unsigned s = h[0][i] + h[1][i];
        if (s) atomicAdd(&gh[(b*perB + (i >> 8))*256 + (i & 255)], s);
    }
}

// ---------------- N_hat + grad mag + gm pass-1 histogram; x-resolve prologue ----------------
__global__ void k_nhat() {
    int b = blockIdx.y;
    __shared__ unsigned h[8*256];
    __shared__ float s_sel[4];
    int warp = threadIdx.x >> 5, lane = threadIdx.x & 31;
    for (int i = threadIdx.x; i < 8*256; i += blockDim.x) h[i] = 0;
    if (warp < 4) {
        unsigned p = chain_prefix(0, b, warp, 4, lane);
        if (lane == 0) s_sel[warp] = __uint_as_float(p);
    }
    __syncthreads();
    float lo = s_sel[0]*(1.0f-FRLO) + s_sel[1]*FRLO;
    float hi = s_sel[2]*(1.0f-FRHI) + s_sel[3]*FRHI;
    float inv = 1.0f / (hi - lo + EPS_C);

    unsigned rep = (threadIdx.x & 7) * 256;
    size_t base = (size_t)b*NPIX;
    for (int idx = blockIdx.x * blockDim.x + threadIdx.x; idx < NPIX; idx += 64*256) {
        int i = idx >> 9, j = idx & 511;
        size_t o = base + idx;
        float xc = __ldg(&g_x[o]);
        float n00 = fminf(fmaxf((xc - lo) * inv, 0.0f), 1.0f);
        float dx = 0.0f, dy = 0.0f;
        if (j < 511) {
            float xr = __ldg(&g_x[o + 1]);
            dx = fminf(fmaxf((xr - lo) * inv, 0.0f), 1.0f) - n00;
        }
        if (i < 511) {
            float xd = __ldg(&g_x[o + 512]);
            dy = fminf(fmaxf((xd - lo) * inv, 0.0f), 1.0f) - n00;
        }
        float gm = sqrtf(dx*dx + dy*dy + EPS_C);
        g_Nh[o] = n00;
        g_gm[o] = gm;
        atomicAdd(&h[rep + (__float_as_uint(gm) >> 24)], 1u);
    }
    __syncthreads();
    for (int i = threadIdx.x; i < 256; i += blockDim.x) {
        unsigned s = 0;
        #pragma unroll
        for (int r = 0; r < 8; r++) s += h[r*256 + i];
        if (s) atomicAdd(&g_hist1g[b*256 + i], s);
    }
}

// ---------------- bounds; gm-resolve prologue (restored from R14) ----------------
__global__ void k_wxy() {
    int b = blockIdx.y;
    __shared__ float s_sel[2];
    int warp = threadIdx.x >> 5, lane = threadIdx.x & 31;
    if (warp < 2) {
        unsigned p = chain_prefix(1, b, warp, 4, lane);
        if (lane == 0) s_sel[warp] = __uint_as_float(p);
    }
    __syncthreads();
    float med = 0.5f * (s_sel[0] + s_sel[1]);
    float isig = 1.0f / fmaxf(med, EPS_C);

    size_t base = (size_t)b*NPIX;
    for (int idx = blockIdx.x * blockDim.x + threadIdx.x; idx < NPIX; idx += 64*256) {
        int i = idx >> 9, j = idx & 511;
        size_t o = base + idx;
        float n00 = __ldg(&g_Nh[o]);
        float dx = (j < 511) ? (__ldg(&g_Nh[o + 1]) - n00) : 0.0f;
        float dy = (i < 511) ? (__ldg(&g_Nh[o + 512]) - n00) : 0.0f;
        g_Wx[o] = ALPHA_C * (1.0f + MU_C * __expf(-fabsf(dx) * isig));
        g_Wy[o] = ALPHA_C * (1.0f + MU_C * __expf(-fabsf(dy) * isig));
    }
}

// ---------------- shuffle-register fused PD (FROZEN: exact R7/R14 body) ----------------
template<bool FIRST, bool LAST>
__global__ void __launch_bounds__(512, 2) k_pdshfl(int rd, int wr, float* __restrict__ out) {
    extern __shared__ float sm[];
    float* s_bx     = sm;
    float* s_by     = sm + SS*SS;
    float* s_tnh    = sm + 2*SS*SS;
    float* s_rowub  = sm + 3*SS*SS;          // [9][SS]
    float* s_rowpy  = s_rowub + 9*SS;        // [9][SS]
    float* s_seamub = s_rowpy + 9*SS;        // [SS]
    float* s_seampx = s_seamub + SS;         // [SS]

    int b = blockIdx.z;
    int rx0 = blockIdx.x * TT - KK;
    int ry0 = blockIdx.y * TT - KK;
    size_t base = (size_t)b * NPIX;
    int tx = threadIdx.x, ty = threadIdx.y;
    int R0 = ty * PPT;
    int gj = rx0 + tx;
    int gi0 = ry0 + R0;
    bool jok = (gj >= 0) && (gj < 512);

    float ru[PPT], rub[PPT], rpx[PPT], rpy[PPT];

    #pragma unroll
    for (int k = 0; k < PPT; k++) {
        int gi = gi0 + k;
        int o = (R0 + k)*SS + tx;
        if (jok && gi >= 0 && gi < 512) {
            size_t go = base + (size_t)gi*512 + gj;
            float nh = __ldg(&g_Nh[go]);
            s_tnh[o] = TAUC * nh;
            s_bx[o]  = __ldg(&g_Wx[go]);
            s_by[o]  = __ldg(&g_Wy[go]);
            if (FIRST) {
                ru[k] = nh; rub[k] = nh; rpx[k] = 0.0f; rpy[k] = 0.0f;
            } else {
                ru[k]  = __ldg(&g_u [rd][go]);
                rub[k] = __ldg(&g_ub[rd][go]);
                rpx[k] = __ldg(&g_px[rd][go]);
                rpy[k] = __ldg(&g_py[rd][go]);
            }
        } else {
            s_tnh[o] = 0.0f; s_bx[o] = 0.0f; s_by[o] = 0.0f;
            ru[k] = 0.0f; rub[k] = 0.0f; rpx[k] = 0.0f; rpy[k] = 0.0f;
        }
    }
    s_rowub[ty*SS + tx] = rub[0];
    if (ty == 0) { s_rowub[8*SS + tx] = 0.0f; s_rowpy[0*SS + tx] = 0.0f; }
    if (tx == 32) {
        #pragma unroll
        for (int k = 0; k < PPT; k++) s_seamub[R0 + k] = rub[k];
    }
    __syncthreads();

    const unsigned FULL = 0xffffffffu;
    bool jlt511 = (gj < 511);
    bool jgt0   = (gj > 0);

    for (int t = 0; t < KK; t++) {
        float ubbelow = s_rowub[(ty+1)*SS + tx];
        #pragma unroll
        for (int k = 0; k < PPT; k++) {
            float ubc = rub[k];
            float ubr = __shfl_down_sync(FULL, ubc, 1);
            if (tx == 31) ubr = s_seamub[R0 + k];
            float ubd = (k < PPT-1) ? rub[k+1] : ubbelow;
            int gi = gi0 + k;
            float dx = jlt511     ? (ubr - ubc) : 0.0f;
            float dy = (gi < 511) ? (ubd - ubc) : 0.0f;
            int o = (R0 + k)*SS + tx;
            float bx = s_bx[o], by = s_by[o];
            rpx[k] = fminf(fmaxf(rpx[k] + SIG*dx, -bx), bx);
            rpy[k] = fminf(fmaxf(rpy[k] + SIG*dy, -by), by);
        }
        s_rowpy[(ty+1)*SS + tx] = rpy[PPT-1];
        if (tx == 31) {
            #pragma unroll
            for (int k = 0; k < PPT; k++) s_seampx[R0 + k] = rpx[k];
        }
        __syncthreads();

        float pyabove = s_rowpy[ty*SS + tx];
        #pragma unroll
        for (int k = 0; k < PPT; k++) {
            float pxc = rpx[k];
            float pxl = __shfl_up_sync(FULL, pxc, 1);
            if (tx == 32) pxl = s_seampx[R0 + k];
            if (!jgt0) pxl = 0.0f;
            float pyu = (k > 0) ? rpy[k-1] : pyabove;
            int gi = gi0 + k;
            if (gi <= 0) pyu = 0.0f;
            int o = (R0 + k)*SS + tx;
            float uc = ru[k];
            float un = (uc + TAUC*(rpx[k] - pxl + rpy[k] - pyu) + s_tnh[o]) * INV1T;
            rub[k] = 2.0f*un - uc;
            ru[k] = un;
        }
        s_rowub[ty*SS + tx] = rub[0];
        if (tx == 32) {
            #pragma unroll
            for (int k = 0; k < PPT; k++) s_seamub[R0 + k] = rub[k];
        }
        __syncthreads();
    }

    if (tx >= KK && tx < KK+TT && gj < 512) {
        #pragma unroll
        for (int k = 0; k < PPT; k++) {
            int r = R0 + k;
            if (r >= KK && r < KK+TT) {
                int gi = gi0 + k;
                if (gi < 512) {
                    size_t go = base + (size_t)gi*512 + gj;
                    if (LAST) {
                        out[go] = fminf(fmaxf(ru[k], 0.0f), 1.0f);
                    } else {
                        g_u [wr][go] = ru[k];
                        g_ub[wr][go] = rub[k];
                        g_px[wr][go] = rpx[k];
                        g_py[wr][go] = rpy[k];
                    }
                }
            }
        }
    }
}

// ---------------- launch (single stream, no device allocations) ----------------
extern "C" void kernel_launch(void* const* d_in, const int* in_sizes, int n_in,
                              void* d_out, int out_size) {
    const float* Iy = (const float*)d_in[0];
    float* out = (float*)d_out;

    const int smbytes = (3*SS*SS + 2*9*SS + 2*SS) * (int)sizeof(float);
    cudaFuncSetAttribute(k_pdshfl<true,false>,  cudaFuncAttributeMaxDynamicSharedMemorySize, smbytes);
    cudaFuncSetAttribute(k_pdshfl<false,false>, cudaFuncAttributeMaxDynamicSharedMemorySize, smbytes);
    cudaFuncSetAttribute(k_pdshfl<false,true>,  cudaFuncAttributeMaxDynamicSharedMemorySize, smbytes);

    dim3 b32x8(32, 8);

    k_hpool  <<<dim3(512, NB), 512>>>(Iy);       // + histogram zeroing fold (no k_zero_hists)
    k_vpool_x<<<dim3(16, 8, NB), b32x8>>>(Iy);   // + x pass-1 histogram

    // x quantiles (resolve chains run inside consumers)
    k_histT<<<dim3(32, NB), 256>>>(0, 2);
    k_histT<<<dim3(32, NB), 256>>>(0, 3);
    k_histT<<<dim3(32, NB), 256>>>(0, 4);

    k_nhat<<<dim3(64, NB), 256>>>();             // x-resolve prologue + gm pass-1

    // gm quantiles
    k_histT<<<dim3(32, NB), 256>>>(1, 2);
    k_histT<<<dim3(32, NB), 256>>>(1, 3);
    k_histT<<<dim3(32, NB), 256>>>(1, 4);

    k_wxy<<<dim3(64, NB), 256>>>();              // gm-resolve prologue (restored)

    // 30 PD iterations = 3 fused launches of 10 (frozen)
    dim3 bTile(SS, 8);
    dim3 gTile(NTILE, NTILE, NB);
    k_pdshfl<true,  false><<<gTile, bTile, smbytes>>>(0, 0, nullptr);
    k_pdshfl<false, false><<<gTile, bTile, smbytes>>>(0, 1, nullptr);
    k_pdshfl<false, true ><<<gTile, bTile, smbytes>>>(1, 0, out);
}

// round 17
// speedup vs baseline: 1.0145x; 1.0072x over previous
#include <cuda_runtime.h>
#include <math.h>

#define NPIX (512*512)
#define NB 16
#define SIG 0.125f
#define TAUC 0.125f
#define ALPHA_C 0.15f
#define MU_C 10.0f
#define EPS_C 1e-6f
#define INV1T (1.0f/1.125f)
#define FRLO 0.43000000000029104f
#define FRHI 0.5699999999953434f

// fused PD tiling (shuffle version, FROZEN R7)
#define TT 44
#define KK 10
#define SS 64
#define PPT 8
#define NTILE 12            // ceil(512/44)

// ---------------- device scratch ----------------
__device__ float g_tmpR[NB*NPIX];
__device__ float g_tmpM[NB*NPIX];
__device__ float g_x  [NB*NPIX];
__device__ float g_Nh [NB*NPIX];
__device__ float g_gm [NB*NPIX];
__device__ float g_Wx [NB*NPIX];   // ALPHA*Wx
__device__ float g_Wy [NB*NPIX];   // ALPHA*Wy
__device__ float g_u [2][NB*NPIX];
__device__ float g_ub[2][NB*NPIX];
__device__ float g_px[2][NB*NPIX];
__device__ float g_py[2][NB*NPIX];

// radix 8+8+8+8 (R7 scheme — final)
__device__ unsigned g_hist1 [NB*256];      // x pass-1
__device__ unsigned g_hist1g[NB*256];      // gm pass-1
__device__ unsigned g_histX[3][64*256];    // x passes 2..4
__device__ unsigned g_histG[3][32*256];    // gm passes 2..4

__constant__ int c_ranksX[4] = {2621, 2622, 259521, 259522};
__constant__ int c_ranksG[2] = {131071, 131072};

// ---------------- zero all histogram buffers ----------------
__global__ void k_zero_hists() {
    unsigned* hx = &g_histX[0][0];
    unsigned* hg = &g_histG[0][0];
    for (int i = blockIdx.x * blockDim.x + threadIdx.x; i < 81920; i += gridDim.x * blockDim.x) {
        if (i < 4096) g_hist1[i] = 0;
        else if (i < 8192) g_hist1g[i - 4096] = 0;
        else if (i < 8192 + 49152) hx[i - 8192] = 0;
        else hg[i - 57344] = 0;
    }
}

// ---------------- warp-collective radix resolve (256-bin) ----------------
__device__ __forceinline__ unsigned warp_resolve_step(const unsigned* hist, unsigned& rank, int lane) {
    unsigned c[8]; unsigned s = 0;
    #pragma unroll
    for (int i = 0; i < 8; i++) { c[i] = __ldg(&hist[lane*8 + i]); s += c[i]; }
    unsigned pre = s;
    #pragma unroll
    for (int d = 1; d < 32; d <<= 1) {
        unsigned v = __shfl_up_sync(0xffffffffu, pre, d);
        if (lane >= d) pre += v;
    }
    unsigned excl = pre - s;
    bool hit = (rank >= excl) && (rank < excl + s);
    unsigned m = __ballot_sync(0xffffffffu, hit);
    int hl = m ? (__ffs(m) - 1) : 31;
    unsigned bkt = 255, rr = 0;
    if (lane == hl) {
        if (m) {
            rr = rank - excl;
            int i = 0;
            while (i < 7 && rr >= c[i]) { rr -= c[i]; i++; }
            bkt = (unsigned)(hl*8 + i);
        } else { bkt = 255; rr = 0; }
    }
    bkt = __shfl_sync(0xffffffffu, bkt, hl);
    rr  = __shfl_sync(0xffffffffu, rr,  hl);
    rank = rr;
    return bkt;
}

__device__ __forceinline__ unsigned chain_prefix(int which, int b, int tgt, int upto, int lane) {
    unsigned rank = which ? (unsigned)c_ranksG[tgt] : (unsigned)c_ranksX[tgt];
    unsigned prefix = 0u;
    for (int pass = 1; pass <= upto; pass++) {
        const unsigned* hist;
        if (pass == 1) hist = (which ? g_hist1g : g_hist1) + b*256;
        else {
            int perB = which ? 2 : 4;
            hist = (which ? &g_histG[pass-2][0] : &g_histX[pass-2][0]) + (b*perB + tgt)*256;
        }
        unsigned bkt = warp_resolve_step(hist, rank, lane);
        prefix |= bkt << (8*(4-pass));
    }
    return prefix;
}

// ---------------- horizontal 31-max-pool ----------------
__global__ void k_hpool(const float* __restrict__ Iy) {
    int row = blockIdx.x, b = blockIdx.y;
    __shared__ float sR[512];
    __shared__ float sM[512];
    int j = threadIdx.x;
    const float* base = Iy + (size_t)b*3*NPIX + (size_t)row*512;
    float r = __ldg(base + j);
    float m = fmaxf(__ldg(base + NPIX + j), __ldg(base + 2*NPIX + j));
    sR[j] = r; sM[j] = m;
    __syncthreads();
    float mr = r, mm = m;
    #pragma unroll
    for (int t = -15; t <= 15; t++) {
        int jj = j + t; jj = jj < 0 ? 0 : (jj > 511 ? 511 : jj);
        mr = fmaxf(mr, sR[jj]);
        mm = fmaxf(mm, sM[jj]);
    }
    size_t o = (size_t)b*NPIX + (size_t)row*512 + j;
    g_tmpR[o] = mr; g_tmpM[o] = mm;
}

// ---------------- vertical 31-max-pool + x + x pass-1 histogram ----------------
__global__ void k_vpool_x(const float* __restrict__ Iy) {
    int b = blockIdx.z;
    int col0 = blockIdx.x * 32;
    int row0 = blockIdx.y * 64;
    __shared__ float sR[94][32];
    __shared__ float sM[94][32];
    __shared__ unsigned h[8*256];
    int tid = threadIdx.y * 32 + threadIdx.x;
    for (int i = tid; i < 8*256; i += 256) h[i] = 0;
    for (int idx = tid; idx < 94*32; idx += 256) {
        int rr = idx >> 5, cc = idx & 31;
        int gr = row0 + rr - 15; gr = gr < 0 ? 0 : (gr > 511 ? 511 : gr);
        size_t o = (size_t)b*NPIX + (size_t)gr*512 + col0 + cc;
        sR[rr][cc] = g_tmpR[o];
        sM[rr][cc] = g_tmpM[o];
    }
    __syncthreads();
    int tx = threadIdx.x;
    unsigned rep = (tid & 7) * 256;
    for (int k = 0; k < 8; k++) {
        int r = threadIdx.y * 8 + k;
        float mr = -1e30f, mm = -1e30f;
        #pragma unroll
        for (int t = 0; t < 31; t++) {
            mr = fmaxf(mr, sR[r+t][tx]);
            mm = fmaxf(mm, sM[r+t][tx]);
        }
        int gr = row0 + r;
        size_t o = (size_t)b*NPIX + (size_t)gr*512 + col0 + tx;
        float R = __ldg(Iy + (size_t)b*3*NPIX + (size_t)gr*512 + col0 + tx);
        float xv = fabsf(mr - mm) + R;
        g_x[o] = xv;
        atomicAdd(&h[rep + (__float_as_uint(xv) >> 24)], 1u);
    }
    __syncthreads();
    for (int i = tid; i < 256; i += 256) {
        unsigned s = 0;
        #pragma unroll
        for (int r = 0; r < 8; r++) s += h[r*256 + i];
        if (s) atomicAdd(&g_hist1[b*256 + i], s);
    }
}

// ---------------- conditional histogram; prefix-chain prologue; MLP-4 main loop ----------------
__global__ void k_histT(int which, int pass) {
    int b = blockIdx.y;
    const int perB = which ? 2 : 4;
    const float* src = which ? g_gm : g_x;
    unsigned* gh = which ? &g_histG[pass-2][0] : &g_histX[pass-2][0];
    int shift = 8 * (4 - pass);
    unsigned mask = 0xFFFFFFFFu << (shift + 8);

    __shared__ unsigned s_pref[4];
    __shared__ unsigned h[2][4*256];
    int warp = threadIdx.x >> 5, lane = threadIdx.x & 31;
    for (int i = threadIdx.x; i < 2*4*256; i += blockDim.x) (&h[0][0])[i] = 0;
    if (warp < perB) {
        unsigned p = chain_prefix(which, b, warp, pass - 1, lane);
        if (lane == 0) s_pref[warp] = p;
    }
    __syncthreads();

    unsigned pref[4];
    #pragma unroll
    for (int j = 0; j < 4; j++) pref[j] = (j < perB) ? s_pref[j] : 0xFFFFFFFFu;

    unsigned rep = threadIdx.x & 1;
    const float4* p = (const float4*)(src + (size_t)b*NPIX);
    const int stride = gridDim.x * blockDim.x;     // 8192
    int i0 = blockIdx.x * blockDim.x + threadIdx.x;
    for (int base_i = i0; base_i < NPIX/4; base_i += 4*stride) {
        float4 v0 = __ldg(p + base_i);
        float4 v1 = __ldg(p + base_i + stride);
        float4 v2 = __ldg(p + base_i + 2*stride);
        float4 v3 = __ldg(p + base_i + 3*stride);
        float4 vv[4] = {v0, v1, v2, v3};
        #pragma unroll
        for (int q = 0; q < 4; q++) {
            unsigned vs[4] = {__float_as_uint(vv[q].x), __float_as_uint(vv[q].y),
                              __float_as_uint(vv[q].z), __float_as_uint(vv[q].w)};
            #pragma unroll
            for (int e = 0; e < 4; e++) {
                unsigned v = vs[e];
                unsigned vm = v & mask;
                unsigned bin = (v >> shift) & 0xFFu;
                #pragma unroll
                for (int j = 0; j < 4; j++)
                    if (j < perB && vm == pref[j]) atomicAdd(&h[rep][j*256 + bin], 1u);
            }
        }
    }
    __syncthreads();
    for (int i = threadIdx.x; i < perB*256; i += blockDim.x) {
        unsigned s = h[0][i] + h[1][i];
        if (s) atomicAdd(&gh[(b*perB + (i >> 8))*256 + (i & 255)], s);
    }
}

// ---------------- N_hat + grad mag + gm pass-1 histogram; x-resolve prologue ----------------
__global__ void k_nhat() {
    int b = blockIdx.y;
    __shared__ unsigned h[8*256];
    __shared__ float s_sel[4];
    int warp = threadIdx.x >> 5, lane = threadIdx.x & 31;
    for (int i = threadIdx.x; i < 8*256; i += blockDim.x) h[i] = 0;
    if (warp < 4) {
        unsigned p = chain_prefix(0, b, warp, 4, lane);
        if (lane == 0) s_sel[warp] = __uint_as_float(p);
    }
    __syncthreads();
    float lo = s_sel[0]*(1.0f-FRLO) + s_sel[1]*FRLO;
    float hi = s_sel[2]*(1.0f-FRHI) + s_sel[3]*FRHI;
    float inv = 1.0f / (hi - lo + EPS_C);

    unsigned rep = (threadIdx.x & 7) * 256;
    size_t base = (size_t)b*NPIX;
    for (int idx = blockIdx.x * blockDim.x + threadIdx.x; idx < NPIX; idx += 64*256) {
        int i = idx >> 9, j = idx & 511;
        size_t o = base + idx;
        float xc = __ldg(&g_x[o]);
        float n00 = fminf(fmaxf((xc - lo) * inv, 0.0f), 1.0f);
        float dx = 0.0f, dy = 0.0f;
        if (j < 511) {
            float xr = __ldg(&g_x[o + 1]);
            dx = fminf(fmaxf((xr - lo) * inv, 0.0f), 1.0f) - n00;
        }
        if (i < 511) {
            float xd = __ldg(&g_x[o + 512]);
            dy = fminf(fmaxf((xd - lo) * inv, 0.0f), 1.0f) - n00;
        }
        float gm = sqrtf(dx*dx + dy*dy + EPS_C);
        g_Nh[o] = n00;
        g_gm[o] = gm;
        atomicAdd(&h[rep + (__float_as_uint(gm) >> 24)], 1u);
    }
    __syncthreads();
    for (int i = threadIdx.x; i < 256; i += blockDim.x) {
        unsigned s = 0;
        #pragma unroll
        for (int r = 0; r < 8; r++) s += h[r*256 + i];
        if (s) atomicAdd(&g_hist1g[b*256 + i], s);
    }
}

// ---------------- bounds; gm-resolve prologue ----------------
__global__ void k_wxy() {
    int b = blockIdx.y;
    __shared__ float s_sel[2];
    int warp = threadIdx.x >> 5, lane = threadIdx.x & 31;
    if (warp < 2) {
        unsigned p = chain_prefix(1, b, warp, 4, lane);
        if (lane == 0) s_sel[warp] = __uint_as_float(p);
    }
    __syncthreads();
    float med = 0.5f * (s_sel[0] + s_sel[1]);
    float isig = 1.0f / fmaxf(med, EPS_C);

    size_t base = (size_t)b*NPIX;
    for (int idx = blockIdx.x * blockDim.x + threadIdx.x; idx < NPIX; idx += 64*256) {
        int i = idx >> 9, j = idx & 511;
        size_t o = base + idx;
        float n00 = __ldg(&g_Nh[o]);
        float dx = (j < 511) ? (__ldg(&g_Nh[o + 1]) - n00) : 0.0f;
        float dy = (i < 511) ? (__ldg(&g_Nh[o + 512]) - n00) : 0.0f;
        g_Wx[o] = ALPHA_C * (1.0f + MU_C * __expf(-fabsf(dx) * isig));
        g_Wy[o] = ALPHA_C * (1.0f + MU_C * __expf(-fabsf(dy) * isig));
    }
}

// ---------------- shuffle-register fused PD (FROZEN: exact R7 body) ----------------
template<bool FIRST, bool LAST>
__global__ void __launch_bounds__(512, 2) k_pdshfl(int rd, int wr, float* __restrict__ out) {
    extern __shared__ float sm[];
    float* s_bx     = sm;
    float* s_by     = sm + SS*SS;
    float* s_tnh    = sm + 2*SS*SS;
    float* s_rowub  = sm + 3*SS*SS;          // [9][SS]
    float* s_rowpy  = s_rowub + 9*SS;        // [9][SS]
    float* s_seamub = s_rowpy + 9*SS;        // [SS]
    float* s_seampx = s_seamub + SS;         // [SS]

    int b = blockIdx.z;
    int rx0 = blockIdx.x * TT - KK;
    int ry0 = blockIdx.y * TT - KK;
    size_t base = (size_t)b * NPIX;
    int tx = threadIdx.x, ty = threadIdx.y;
    int R0 = ty * PPT;
    int gj = rx0 + tx;
    int gi0 = ry0 + R0;
    bool jok = (gj >= 0) && (gj < 512);

    float ru[PPT], rub[PPT], rpx[PPT], rpy[PPT];

    #pragma unroll
    for (int k = 0; k < PPT; k++) {
        int gi = gi0 + k;
        int o = (R0 + k)*SS + tx;
        if (jok && gi >= 0 && gi < 512) {
            size_t go = base + (size_t)gi*512 + gj;
            float nh = __ldg(&g_Nh[go]);
            s_tnh[o] = TAUC * nh;
            s_bx[o]  = __ldg(&g_Wx[go]);
            s_by[o]  = __ldg(&g_Wy[go]);
            if (FIRST) {
                ru[k] = nh; rub[k] = nh; rpx[k] = 0.0f; rpy[k] = 0.0f;
            } else {
                ru[k]  = __ldg(&g_u [rd][go]);
                rub[k] = __ldg(&g_ub[rd][go]);
                rpx[k] = __ldg(&g_px[rd][go]);
                rpy[k] = __ldg(&g_py[rd][go]);
            }
        } else {
            s_tnh[o] = 0.0f; s_bx[o] = 0.0f; s_by[o] = 0.0f;
            ru[k] = 0.0f; rub[k] = 0.0f; rpx[k] = 0.0f; rpy[k] = 0.0f;
        }
    }
    s_rowub[ty*SS + tx] = rub[0];
    if (ty == 0) { s_rowub[8*SS + tx] = 0.0f; s_rowpy[0*SS + tx] = 0.0f; }
    if (tx == 32) {
        #pragma unroll
        for (int k = 0; k < PPT; k++) s_seamub[R0 + k] = rub[k];
    }
    __syncthreads();

    const unsigned FULL = 0xffffffffu;
    bool jlt511 = (gj < 511);
    bool jgt0   = (gj > 0);

    for (int t = 0; t < KK; t++) {
        float ubbelow = s_rowub[(ty+1)*SS + tx];
        #pragma unroll
        for (int k = 0; k < PPT; k++) {
            float ubc = rub[k];
            float ubr = __shfl_down_sync(FULL, ubc, 1);
            if (tx == 31) ubr = s_seamub[R0 + k];
            float ubd = (k < PPT-1) ? rub[k+1] : ubbelow;
            int gi = gi0 + k;
            float dx = jlt511     ? (ubr - ubc) : 0.0f;
            float dy = (gi < 511) ? (ubd - ubc) : 0.0f;
            int o = (R0 + k)*SS + tx;
            float bx = s_bx[o], by = s_by[o];
            rpx[k] = fminf(fmaxf(rpx[k] + SIG*dx, -bx), bx);
            rpy[k] = fminf(fmaxf(rpy[k] + SIG*dy, -by), by);
        }
        s_rowpy[(ty+1)*SS + tx] = rpy[PPT-1];
        if (tx == 31) {
            #pragma unroll
            for (int k = 0; k < PPT; k++) s_seampx[R0 + k] = rpx[k];
        }
        __syncthreads();

        float pyabove = s_rowpy[ty*SS + tx];
        #pragma unroll
        for (int k = 0; k < PPT; k++) {
            float pxc = rpx[k];
            float pxl = __shfl_up_sync(FULL, pxc, 1);
            if (tx == 32) pxl = s_seampx[R0 + k];
            if (!jgt0) pxl = 0.0f;
            float pyu = (k > 0) ? rpy[k-1] : pyabove;
            int gi = gi0 + k;
            if (gi <= 0) pyu = 0.0f;
            int o = (R0 + k)*SS + tx;
            float uc = ru[k];
            float un = (uc + TAUC*(rpx[k] - pxl + rpy[k] - pyu) + s_tnh[o]) * INV1T;
            rub[k] = 2.0f*un - uc;
            ru[k] = un;
        }
        s_rowub[ty*SS + tx] = rub[0];
        if (tx == 32) {
            #pragma unroll
            for (int k = 0; k < PPT; k++) s_seamub[R0 + k] = rub[k];
        }
        __syncthreads();
    }

    if (tx >= KK && tx < KK+TT && gj < 512) {
        #pragma unroll
        for (int k = 0; k < PPT; k++) {
            int r = R0 + k;
            if (r >= KK && r < KK+TT) {
                int gi = gi0 + k;
                if (gi < 512) {
                    size_t go = base + (size_t)gi*512 + gj;
                    if (LAST) {
                        out[go] = fminf(fmaxf(ru[k], 0.0f), 1.0f);
                    } else {
                        g_u [wr][go] = ru[k];
                        g_ub[wr][go] = rub[k];
                        g_px[wr][go] = rpx[k];
                        g_py[wr][go] = rpy[k];
                    }
                }
            }
        }
    }
}

// ---------------- launch (single stream, no device allocations) ----------------
extern "C" void kernel_launch(void* const* d_in, const int* in_sizes, int n_in,
                              void* d_out, int out_size) {
    const float* Iy = (const float*)d_in[0];
    float* out = (float*)d_out;

    const int smbytes = (3*SS*SS + 2*9*SS + 2*SS) * (int)sizeof(float);
    cudaFuncSetAttribute(k_pdshfl<true,false>,  cudaFuncAttributeMaxDynamicSharedMemorySize, smbytes);
    cudaFuncSetAttribute(k_pdshfl<false,false>, cudaFuncAttributeMaxDynamicSharedMemorySize, smbytes);
    cudaFuncSetAttribute(k_pdshfl<false,true>,  cudaFuncAttributeMaxDynamicSharedMemorySize, smbytes);

    dim3 b32x8(32, 8);

    k_zero_hists<<<64, 256>>>();
    k_hpool  <<<dim3(512, NB), 512>>>(Iy);
    k_vpool_x<<<dim3(16, 8, NB), b32x8>>>(Iy);   // + x pass-1 histogram

    // x quantiles (resolve chains run inside consumers)
    k_histT<<<dim3(32, NB), 256>>>(0, 2);
    k_histT<<<dim3(32, NB), 256>>>(0, 3);
    k_histT<<<dim3(32, NB), 256>>>(0, 4);

    k_nhat<<<dim3(64, NB), 256>>>();             // x-resolve prologue + gm pass-1

    // gm quantiles
    k_histT<<<dim3(32, NB), 256>>>(1, 2);
    k_histT<<<dim3(32, NB), 256>>>(1, 3);
    k_histT<<<dim3(32, NB), 256>>>(1, 4);

    k_wxy<<<dim3(64, NB), 256>>>();              // gm-resolve prologue

    // 30 PD iterations = 3 fused launches of 10
    dim3 bTile(SS, 8);
    dim3 gTile(NTILE, NTILE, NB);
    k_pdshfl<true,  false><<<gTile, bTile, smbytes>>>(0, 0, nullptr);
    k_pdshfl<false, false><<<gTile, bTile, smbytes>>>(0, 1, nullptr);
    k_pdshfl<false, true ><<<gTile, bTile, smbytes>>>(1, 0, out);
}